// round 1
// baseline (speedup 1.0000x reference)
#include <cuda_runtime.h>
#include <cuda_bf16.h>
#include <math.h>

// Problem constants
#define B_  4
#define N_  1024
#define E_  1024
#define H_  16
#define D_  64
#define MTOT (B_ * N_)        // 4096 rows for projections

// -------- scratch (device globals; no allocation allowed) ----------
__device__ float g_Q[MTOT * E_];            // 16 MB
__device__ float g_K[MTOT * E_];            // 16 MB
__device__ float g_V[MTOT * E_];            // 16 MB
__device__ float g_CTX[MTOT * E_];          // 16 MB
__device__ float g_S[(long)B_ * H_ * N_ * N_];   // 256 MB energy / attention

// ====================================================================
// Tiled GEMM, C = A * B^T (+bias), A:[M,K] row-major (lda), B:[N,K]
// row-major (ldb).  Batched: z = z1*nb2 + z2, offsets z1*s?1 + z2*s?2.
// BM=BN=64, BK=16, 256 threads, 4x4 per thread.
// ====================================================================
#define BM 64
#define BN 64
#define BK 16

__global__ __launch_bounds__(256)
void gemm_nt(const float* __restrict__ A, const float* __restrict__ B,
             const float* __restrict__ bias, float* __restrict__ C,
             int M, int N, int K, int lda, int ldb, int ldc,
             long sA1, long sA2, long sB1, long sB2, long sC1, long sC2,
             int nb2)
{
    int z = blockIdx.z;
    int z1 = z / nb2, z2 = z % nb2;
    A += z1 * sA1 + z2 * sA2;
    B += z1 * sB1 + z2 * sB2;
    C += z1 * sC1 + z2 * sC2;

    __shared__ float As[BK][BM];
    __shared__ float Bs[BK][BN];

    const int tid = threadIdx.x;
    const int tx = tid & 15;        // 0..15 -> N direction
    const int ty = tid >> 4;        // 0..15 -> M direction
    const int row0 = blockIdx.y * BM;
    const int col0 = blockIdx.x * BN;

    float acc[4][4] = {};

    for (int k0 = 0; k0 < K; k0 += BK) {
        // load A tile (64 rows x 16 k), k contiguous in gmem
        #pragma unroll
        for (int i = 0; i < 4; i++) {
            int idx = tid + i * 256;
            int m = idx >> 4, kk = idx & 15;
            As[kk][m] = A[(long)(row0 + m) * lda + k0 + kk];
        }
        // load B tile (64 n-rows x 16 k), k contiguous in gmem
        #pragma unroll
        for (int i = 0; i < 4; i++) {
            int idx = tid + i * 256;
            int n = idx >> 4, kk = idx & 15;
            Bs[kk][n] = B[(long)(col0 + n) * ldb + k0 + kk];
        }
        __syncthreads();

        #pragma unroll
        for (int kk = 0; kk < BK; kk++) {
            float4 av = *reinterpret_cast<const float4*>(&As[kk][ty * 4]);
            float4 bv = *reinterpret_cast<const float4*>(&Bs[kk][tx * 4]);
            float a[4] = {av.x, av.y, av.z, av.w};
            float b[4] = {bv.x, bv.y, bv.z, bv.w};
            #pragma unroll
            for (int i = 0; i < 4; i++)
                #pragma unroll
                for (int j = 0; j < 4; j++)
                    acc[i][j] += a[i] * b[j];
        }
        __syncthreads();
    }

    #pragma unroll
    for (int i = 0; i < 4; i++) {
        int r = row0 + ty * 4 + i;
        #pragma unroll
        for (int j = 0; j < 4; j++) {
            int c = col0 + tx * 4 + j;
            float v = acc[i][j];
            if (bias) v += bias[c];
            C[(long)r * ldc + c] = v;
        }
    }
}

// ====================================================================
// Tiled GEMM, C = A * B (+nothing), A:[M,K] row-major, B:[K,N] row-major.
// Used for att @ V  (M=1024, N=64, K=1024 per (b,h)).
// ====================================================================
__global__ __launch_bounds__(256)
void gemm_nn(const float* __restrict__ A, const float* __restrict__ B,
             float* __restrict__ C,
             int M, int N, int K, int lda, int ldb, int ldc,
             long sA1, long sA2, long sB1, long sB2, long sC1, long sC2,
             int nb2)
{
    int z = blockIdx.z;
    int z1 = z / nb2, z2 = z % nb2;
    A += z1 * sA1 + z2 * sA2;
    B += z1 * sB1 + z2 * sB2;
    C += z1 * sC1 + z2 * sC2;

    __shared__ float As[BK][BM];
    __shared__ float Bs[BK][BN];

    const int tid = threadIdx.x;
    const int tx = tid & 15;
    const int ty = tid >> 4;
    const int row0 = blockIdx.y * BM;
    const int col0 = blockIdx.x * BN;

    float acc[4][4] = {};

    for (int k0 = 0; k0 < K; k0 += BK) {
        #pragma unroll
        for (int i = 0; i < 4; i++) {
            int idx = tid + i * 256;
            int m = idx >> 4, kk = idx & 15;
            As[kk][m] = A[(long)(row0 + m) * lda + k0 + kk];
        }
        // B tile: 16 k-rows x 64 n, n contiguous in gmem
        #pragma unroll
        for (int i = 0; i < 4; i++) {
            int idx = tid + i * 256;
            int n = idx & 63, kk = idx >> 6;
            Bs[kk][n] = B[(long)(k0 + kk) * ldb + col0 + n];
        }
        __syncthreads();

        #pragma unroll
        for (int kk = 0; kk < BK; kk++) {
            float4 av = *reinterpret_cast<const float4*>(&As[kk][ty * 4]);
            float4 bv = *reinterpret_cast<const float4*>(&Bs[kk][tx * 4]);
            float a[4] = {av.x, av.y, av.z, av.w};
            float b[4] = {bv.x, bv.y, bv.z, bv.w};
            #pragma unroll
            for (int i = 0; i < 4; i++)
                #pragma unroll
                for (int j = 0; j < 4; j++)
                    acc[i][j] += a[i] * b[j];
        }
        __syncthreads();
    }

    #pragma unroll
    for (int i = 0; i < 4; i++) {
        int r = row0 + ty * 4 + i;
        #pragma unroll
        for (int j = 0; j < 4; j++) {
            int c = col0 + tx * 4 + j;
            C[(long)r * ldc + c] = acc[i][j];
        }
    }
}

// ====================================================================
// Row softmax over 1024 elements, in place, then divide by sqrt(E)=32.
// One block (256 threads) per row.
// ====================================================================
__global__ __launch_bounds__(256)
void softmax_rows(float* __restrict__ S)
{
    float* row = S + (long)blockIdx.x * N_;
    const int tid = threadIdx.x;

    __shared__ float shm[8];
    __shared__ float shs[8];

    float vals[4];
    float m = -INFINITY;
    #pragma unroll
    for (int i = 0; i < 4; i++) {
        vals[i] = row[tid + i * 256];
        m = fmaxf(m, vals[i]);
    }
    // block max
    #pragma unroll
    for (int o = 16; o > 0; o >>= 1) m = fmaxf(m, __shfl_xor_sync(0xffffffffu, m, o));
    if ((tid & 31) == 0) shm[tid >> 5] = m;
    __syncthreads();
    if (tid < 32) {
        float v = (tid < 8) ? shm[tid] : -INFINITY;
        #pragma unroll
        for (int o = 4; o > 0; o >>= 1) v = fmaxf(v, __shfl_xor_sync(0xffffffffu, v, o));
        if (tid == 0) shm[0] = v;
    }
    __syncthreads();
    m = shm[0];

    float s = 0.f;
    #pragma unroll
    for (int i = 0; i < 4; i++) {
        vals[i] = __expf(vals[i] - m);
        s += vals[i];
    }
    // block sum
    #pragma unroll
    for (int o = 16; o > 0; o >>= 1) s += __shfl_xor_sync(0xffffffffu, s, o);
    if ((tid & 31) == 0) shs[tid >> 5] = s;
    __syncthreads();
    if (tid < 32) {
        float v = (tid < 8) ? shs[tid] : 0.f;
        #pragma unroll
        for (int o = 4; o > 0; o >>= 1) v += __shfl_xor_sync(0xffffffffu, v, o);
        if (tid == 0) shs[0] = v;
    }
    __syncthreads();
    s = shs[0];

    // softmax, then divide by sqrt(E)=32 (reference applies scaling AFTER softmax)
    float inv = 1.0f / (s * 32.0f);
    #pragma unroll
    for (int i = 0; i < 4; i++)
        row[tid + i * 256] = vals[i] * inv;
}

// ====================================================================
// launch
// ====================================================================
extern "C" void kernel_launch(void* const* d_in, const int* in_sizes, int n_in,
                              void* d_out, int out_size)
{
    const float* x  = (const float*)d_in[0];
    const float* Wq = (const float*)d_in[1];
    const float* bq = (const float*)d_in[2];
    const float* Wk = (const float*)d_in[3];
    const float* bk = (const float*)d_in[4];
    const float* Wv = (const float*)d_in[5];
    const float* bv = (const float*)d_in[6];
    const float* Wo = (const float*)d_in[7];
    const float* bo = (const float*)d_in[8];
    float* out = (float*)d_out;

    float *Q, *K, *V, *CTX, *S;
    cudaGetSymbolAddress((void**)&Q,   g_Q);
    cudaGetSymbolAddress((void**)&K,   g_K);
    cudaGetSymbolAddress((void**)&V,   g_V);
    cudaGetSymbolAddress((void**)&CTX, g_CTX);
    cudaGetSymbolAddress((void**)&S,   g_S);

    const long NE  = (long)N_ * E_;        // 1,048,576
    const long NN  = (long)N_ * N_;        // 1,048,576
    const long HNN = (long)H_ * NN;        // 16,777,216

    // Q/K/V projections:  [4096,1024] = x[4096,1024] @ W^T + b
    {
        dim3 grid(E_ / BN, MTOT / BM, 1);
        gemm_nt<<<grid, 256>>>(x, Wq, bq, Q, MTOT, E_, E_, E_, E_, E_,
                               0, 0, 0, 0, 0, 0, 1);
        gemm_nt<<<grid, 256>>>(x, Wk, bk, K, MTOT, E_, E_, E_, E_, E_,
                               0, 0, 0, 0, 0, 0, 1);
        gemm_nt<<<grid, 256>>>(x, Wv, bv, V, MTOT, E_, E_, E_, E_, E_,
                               0, 0, 0, 0, 0, 0, 1);
    }

    // energy: per (b,h)  S = q @ k^T   (M=N=1024, K=64)
    {
        dim3 grid(N_ / BN, N_ / BM, B_ * H_);
        gemm_nt<<<grid, 256>>>(Q, K, nullptr, S, N_, N_, D_, E_, E_, N_,
                               NE, (long)D_,     // A: b stride, h stride
                               NE, (long)D_,     // B: b stride, h stride
                               HNN, NN,          // C: b stride, h stride
                               H_);
    }

    // softmax rows (+ /sqrt(E) after softmax)
    {
        softmax_rows<<<B_ * H_ * N_, 256>>>(S);
    }

    // ctx: per (b,h)  ctx = att @ v   (M=1024, N=64, K=1024)
    {
        dim3 grid(D_ / BN, N_ / BM, B_ * H_);   // D_/BN = 1
        gemm_nn<<<grid, 256>>>(S, V, CTX, N_, D_, N_, N_, E_, E_,
                               HNN, NN,          // A(att): b, h strides
                               NE, (long)D_,     // B(V):   b, h strides
                               NE, (long)D_,     // C(ctx): b, h strides
                               H_);
    }

    // output projection: out = ctx @ Wo^T + bo
    {
        dim3 grid(E_ / BN, MTOT / BM, 1);
        gemm_nt<<<grid, 256>>>(CTX, Wo, bo, out, MTOT, E_, E_, E_, E_, E_,
                               0, 0, 0, 0, 0, 0, 1);
    }
}

// round 3
// speedup vs baseline: 2.8126x; 2.8126x over previous
#include <cuda_runtime.h>
#include <cuda_bf16.h>
#include <cstdint>
#include <math.h>

// Problem constants
#define B_  4
#define N_  1024
#define E_  1024
#define H_  16
#define D_  64
#define MTOT (B_ * N_)   // 4096
#define BHN  (B_ * H_)   // 64

// ==================== mma.sync / ldmatrix helpers (sm_80+ PTX, safe on sm_103) ====================
__device__ __forceinline__ uint32_t smem_to_u32(const void* p) {
    uint32_t a;
    asm("{ .reg .u64 t; cvta.to.shared.u64 t, %1; cvt.u32.u64 %0, t; }" : "=r"(a) : "l"(p));
    return a;
}
#define LDSM_X4(R, ADDR) \
    asm volatile("ldmatrix.sync.aligned.m8n8.x4.shared.b16 {%0,%1,%2,%3}, [%4];" \
        : "=r"((R)[0]), "=r"((R)[1]), "=r"((R)[2]), "=r"((R)[3]) : "r"(ADDR))
#define MMA_BF16(D, A, B0, B1) \
    asm volatile("mma.sync.aligned.m16n8k16.row.col.f32.bf16.bf16.f32 " \
        "{%0,%1,%2,%3}, {%4,%5,%6,%7}, {%8,%9}, {%0,%1,%2,%3};" \
        : "+f"((D)[0]), "+f"((D)[1]), "+f"((D)[2]), "+f"((D)[3]) \
        : "r"((A)[0]), "r"((A)[1]), "r"((A)[2]), "r"((A)[3]), "r"(B0), "r"(B1))

// ==================== scratch (device globals) ====================
__device__ __nv_bfloat16 g_xhi[MTOT * E_], g_xlo[MTOT * E_];
__device__ __nv_bfloat16 g_wqh[E_ * E_], g_wql[E_ * E_];
__device__ __nv_bfloat16 g_wkh[E_ * E_], g_wkl[E_ * E_];
__device__ __nv_bfloat16 g_wvh[E_ * E_], g_wvl[E_ * E_];
__device__ __nv_bfloat16 g_woh[E_ * E_], g_wol[E_ * E_];
__device__ __nv_bfloat16 g_qhi[MTOT * E_], g_qlo[MTOT * E_];
__device__ __nv_bfloat16 g_khi[MTOT * E_], g_klo[MTOT * E_];
__device__ __nv_bfloat16 g_vthi[BHN * D_ * N_], g_vtlo[BHN * D_ * N_];  // V^T: [bh][d][tok]
__device__ float        g_S[(long)BHN * N_ * N_];                        // 256 MB energies
__device__ __nv_bfloat16 g_ahi[(long)BHN * N_ * N_], g_alo[(long)BHN * N_ * N_];
__device__ __nv_bfloat16 g_chi[MTOT * E_], g_clo[MTOT * E_];

// ==================== fp32 -> bf16 hi/lo split ====================
__global__ __launch_bounds__(256)
void split_bf16(const float* __restrict__ in, __nv_bfloat16* __restrict__ hi,
                __nv_bfloat16* __restrict__ lo, int n)
{
    int i = (blockIdx.x * 256 + threadIdx.x) * 4;
    if (i >= n) return;
    float4 v = *reinterpret_cast<const float4*>(in + i);
    float vv[4] = {v.x, v.y, v.z, v.w};
    #pragma unroll
    for (int j = 0; j < 4; j++) {
        __nv_bfloat16 h = __float2bfloat16(vv[j]);
        float r = vv[j] - __bfloat162float(h);
        hi[i + j] = h;
        lo[i + j] = __float2bfloat16(r);
    }
}

// ==================== split-bf16 warp-tiled mma.sync GEMM ====================
// C[M,N] = (Ah+Al)[M,K] @ (Bh+Bl)[N,K]^T (+bias).  Both operands K-major.
// BM=128, BN template (128 or 64), BK=32. 256 threads = 8 warps (4 M x 2 N).
// mode: 0 = fp32 store, 1 = bf16 hi/lo store, 2 = V-transpose bf16 hi/lo store
template <int BN_>
__global__ void __launch_bounds__(256)
gemm_mma(const __nv_bfloat16* __restrict__ Ah, const __nv_bfloat16* __restrict__ Al,
         const __nv_bfloat16* __restrict__ Bh, const __nv_bfloat16* __restrict__ Bl,
         const float* __restrict__ bias,
         float* __restrict__ Cf, __nv_bfloat16* __restrict__ Chi, __nv_bfloat16* __restrict__ Clo,
         int K, int lda, int ldb, int ldc,
         long sA1, long sA2, long sB1, long sB2, long sC1, long sC2,
         int nb2, int mode)
{
    constexpr int WN   = BN_ / 2;       // per-warp N extent
    constexpr int NFR  = WN / 8;        // n-fragments per warp (8 or 4)
    constexpr int STR  = 80;            // padded smem row stride (bytes) — conflict-free ldmatrix
    constexpr int SA_HI = 0;
    constexpr int SA_LO = 128 * STR;            // 10240
    constexpr int SB_HI = 2 * 128 * STR;        // 20480
    constexpr int SB_LO = SB_HI + BN_ * STR;
    constexpr int BCH  = (BN_ * 4) / 256;       // B 16B-chunks per thread per tile

    __shared__ char smem[SB_HI + 2 * BN_ * STR];
    const uint32_t sbase = smem_to_u32(smem);

    const int tid  = threadIdx.x;
    const int warp = tid >> 5;
    const int lane = tid & 31;
    const int wm = warp & 3;            // 0..3 -> M
    const int wn = warp >> 2;           // 0..1 -> N

    const int z = blockIdx.z;
    const int z1 = z / nb2, z2 = z - z1 * nb2;
    Ah += z1 * sA1 + z2 * sA2;  Al += z1 * sA1 + z2 * sA2;
    Bh += z1 * sB1 + z2 * sB2;  Bl += z1 * sB1 + z2 * sB2;
    const long coff = z1 * sC1 + z2 * sC2;

    const int row0 = blockIdx.y * 128;
    const int col0 = blockIdx.x * BN_;

    // ldmatrix lane->address mapping (x4: m0,m1 = rows 0-7/8-15 of k0-7; m2,m3 = same rows k8-15)
    const int lrow = (lane & 7) | (((lane >> 3) & 1) << 3);
    const int lk8b = (lane >> 4) * 16;  // byte offset of k-halve

    float acc[2][NFR][4];
    #pragma unroll
    for (int mi = 0; mi < 2; mi++)
        #pragma unroll
        for (int nj = 0; nj < NFR; nj++)
            #pragma unroll
            for (int r = 0; r < 4; r++) acc[mi][nj][r] = 0.f;

    const int nch = K >> 5;
    for (int kc = 0; kc < nch; kc++) {
        // ---- global -> smem (16B vector copies) ----
        const __nv_bfloat16* pAh = Ah + (long)row0 * lda + kc * 32;
        const __nv_bfloat16* pAl = Al + (long)row0 * lda + kc * 32;
        #pragma unroll
        for (int i = 0; i < 2; i++) {
            int c = tid + i * 256;          // 0..511
            int r = c >> 2, k8 = c & 3;
            uint32_t so = r * STR + k8 * 16;
            *reinterpret_cast<uint4*>(smem + SA_HI + so) =
                *reinterpret_cast<const uint4*>(pAh + (long)r * lda + k8 * 8);
            *reinterpret_cast<uint4*>(smem + SA_LO + so) =
                *reinterpret_cast<const uint4*>(pAl + (long)r * lda + k8 * 8);
        }
        const __nv_bfloat16* pBh = Bh + (long)col0 * ldb + kc * 32;
        const __nv_bfloat16* pBl = Bl + (long)col0 * ldb + kc * 32;
        #pragma unroll
        for (int i = 0; i < BCH; i++) {
            int c = tid + i * 256;
            int r = c >> 2, k8 = c & 3;
            uint32_t so = r * STR + k8 * 16;
            *reinterpret_cast<uint4*>(smem + SB_HI + so) =
                *reinterpret_cast<const uint4*>(pBh + (long)r * ldb + k8 * 8);
            *reinterpret_cast<uint4*>(smem + SB_LO + so) =
                *reinterpret_cast<const uint4*>(pBl + (long)r * ldb + k8 * 8);
        }
        __syncthreads();

        // ---- mma phase: two k16 steps ----
        #pragma unroll
        for (int ks = 0; ks < 2; ks++) {
            uint32_t aH[2][4], aL[2][4];
            #pragma unroll
            for (int mi = 0; mi < 2; mi++) {
                uint32_t ao = sbase + SA_HI
                            + (uint32_t)(wm * 32 + mi * 16 + lrow) * STR + ks * 32 + lk8b;
                LDSM_X4(aH[mi], ao);
                LDSM_X4(aL[mi], ao + (SA_LO - SA_HI));
            }
            #pragma unroll
            for (int nj = 0; nj < NFR / 2; nj++) {
                uint32_t bo = sbase + SB_HI
                            + (uint32_t)(wn * WN + nj * 16 + lrow) * STR + ks * 32 + lk8b;
                uint32_t bH[4], bL[4];
                LDSM_X4(bH, bo);
                LDSM_X4(bL, bo + (uint32_t)(BN_ * STR));
                #pragma unroll
                for (int mi = 0; mi < 2; mi++) {
                    MMA_BF16(acc[mi][2 * nj],     aH[mi], bH[0], bH[2]);
                    MMA_BF16(acc[mi][2 * nj],     aH[mi], bL[0], bL[2]);
                    MMA_BF16(acc[mi][2 * nj],     aL[mi], bH[0], bH[2]);
                    MMA_BF16(acc[mi][2 * nj + 1], aH[mi], bH[1], bH[3]);
                    MMA_BF16(acc[mi][2 * nj + 1], aH[mi], bL[1], bL[3]);
                    MMA_BF16(acc[mi][2 * nj + 1], aL[mi], bH[1], bH[3]);
                }
            }
        }
        __syncthreads();
    }

    // ---- epilogue ----
    #pragma unroll
    for (int mi = 0; mi < 2; mi++) {
        int rg = row0 + wm * 32 + mi * 16 + (lane >> 2);
        #pragma unroll
        for (int nj = 0; nj < NFR; nj++) {
            int cg = col0 + wn * WN + nj * 8 + (lane & 3) * 2;
            #pragma unroll
            for (int rr = 0; rr < 2; rr++) {        // row / row+8
                int m = rg + rr * 8;
                #pragma unroll
                for (int cc = 0; cc < 2; cc++) {    // col / col+1
                    int col = cg + cc;
                    float v = acc[mi][nj][rr * 2 + cc];
                    if (bias) v += bias[col];
                    if (mode == 0) {
                        Cf[coff + (long)m * ldc + col] = v;
                    } else if (mode == 1) {
                        __nv_bfloat16 h = __float2bfloat16(v);
                        float r = v - __bfloat162float(h);
                        long o = coff + (long)m * ldc + col;
                        Chi[o] = h;
                        Clo[o] = __float2bfloat16(r);
                    } else {
                        // V-transpose store: row m = b*1024+tok, col = h*64+d -> [b*H+h][d][tok]
                        int hh = col >> 6, dc = col & 63;
                        int b = m >> 10, tok = m & 1023;
                        long o = ((long)(b * H_ + hh) * D_ + dc) * N_ + tok;
                        __nv_bfloat16 h = __float2bfloat16(v);
                        float r = v - __bfloat162float(h);
                        Chi[o] = h;
                        Clo[o] = __float2bfloat16(r);
                    }
                }
            }
        }
    }
}

// ==================== softmax (fp32 in -> bf16 hi/lo out, /32 folded) ====================
__global__ __launch_bounds__(256)
void softmax_rows(const float* __restrict__ S,
                  __nv_bfloat16* __restrict__ Ahi, __nv_bfloat16* __restrict__ Alo)
{
    const float* row = S + (long)blockIdx.x * N_;
    const int tid = threadIdx.x;

    __shared__ float shm[8];
    __shared__ float shs[8];

    float vals[4];
    float m = -INFINITY;
    #pragma unroll
    for (int i = 0; i < 4; i++) {
        vals[i] = row[tid + i * 256];
        m = fmaxf(m, vals[i]);
    }
    #pragma unroll
    for (int o = 16; o > 0; o >>= 1) m = fmaxf(m, __shfl_xor_sync(0xffffffffu, m, o));
    if ((tid & 31) == 0) shm[tid >> 5] = m;
    __syncthreads();
    if (tid < 32) {
        float v = (tid < 8) ? shm[tid] : -INFINITY;
        #pragma unroll
        for (int o = 4; o > 0; o >>= 1) v = fmaxf(v, __shfl_xor_sync(0xffffffffu, v, o));
        if (tid == 0) shm[0] = v;
    }
    __syncthreads();
    m = shm[0];

    float s = 0.f;
    #pragma unroll
    for (int i = 0; i < 4; i++) {
        vals[i] = __expf(vals[i] - m);
        s += vals[i];
    }
    #pragma unroll
    for (int o = 16; o > 0; o >>= 1) s += __shfl_xor_sync(0xffffffffu, s, o);
    if ((tid & 31) == 0) shs[tid >> 5] = s;
    __syncthreads();
    if (tid < 32) {
        float v = (tid < 8) ? shs[tid] : 0.f;
        #pragma unroll
        for (int o = 4; o > 0; o >>= 1) v += __shfl_xor_sync(0xffffffffu, v, o);
        if (tid == 0) shs[0] = v;
    }
    __syncthreads();
    s = shs[0];

    const float inv = 1.0f / (s * 32.0f);  // reference scales AFTER softmax
    const long ro = (long)blockIdx.x * N_;
    #pragma unroll
    for (int i = 0; i < 4; i++) {
        float v = vals[i] * inv;
        __nv_bfloat16 h = __float2bfloat16(v);
        float r = v - __bfloat162float(h);
        long o = ro + tid + i * 256;
        Ahi[o] = h;
        Alo[o] = __float2bfloat16(r);
    }
}

// ==================== launch ====================
extern "C" void kernel_launch(void* const* d_in, const int* in_sizes, int n_in,
                              void* d_out, int out_size)
{
    const float* x  = (const float*)d_in[0];
    const float* Wq = (const float*)d_in[1];
    const float* bq = (const float*)d_in[2];
    const float* Wk = (const float*)d_in[3];
    const float* bk = (const float*)d_in[4];
    const float* Wv = (const float*)d_in[5];
    const float* bv = (const float*)d_in[6];
    const float* Wo = (const float*)d_in[7];
    const float* bo = (const float*)d_in[8];
    float* out = (float*)d_out;

    __nv_bfloat16 *xhi, *xlo, *wqh, *wql, *wkh, *wkl, *wvh, *wvl, *woh, *wol;
    __nv_bfloat16 *qhi, *qlo, *khi, *klo, *vthi, *vtlo, *ahi, *alo, *chi, *clo;
    float* S;
    cudaGetSymbolAddress((void**)&xhi, g_xhi);   cudaGetSymbolAddress((void**)&xlo, g_xlo);
    cudaGetSymbolAddress((void**)&wqh, g_wqh);   cudaGetSymbolAddress((void**)&wql, g_wql);
    cudaGetSymbolAddress((void**)&wkh, g_wkh);   cudaGetSymbolAddress((void**)&wkl, g_wkl);
    cudaGetSymbolAddress((void**)&wvh, g_wvh);   cudaGetSymbolAddress((void**)&wvl, g_wvl);
    cudaGetSymbolAddress((void**)&woh, g_woh);   cudaGetSymbolAddress((void**)&wol, g_wol);
    cudaGetSymbolAddress((void**)&qhi, g_qhi);   cudaGetSymbolAddress((void**)&qlo, g_qlo);
    cudaGetSymbolAddress((void**)&khi, g_khi);   cudaGetSymbolAddress((void**)&klo, g_klo);
    cudaGetSymbolAddress((void**)&vthi, g_vthi); cudaGetSymbolAddress((void**)&vtlo, g_vtlo);
    cudaGetSymbolAddress((void**)&ahi, g_ahi);   cudaGetSymbolAddress((void**)&alo, g_alo);
    cudaGetSymbolAddress((void**)&chi, g_chi);   cudaGetSymbolAddress((void**)&clo, g_clo);
    cudaGetSymbolAddress((void**)&S, g_S);

    const long NE  = (long)N_ * E_;   // 1M
    const long NN  = (long)N_ * N_;   // 1M
    const long HNN = (long)H_ * NN;   // 16M

    // ---- split inputs/weights to bf16 hi/lo ----
    split_bf16<<<(MTOT * E_) / 1024, 256>>>(x, xhi, xlo, MTOT * E_);
    split_bf16<<<(E_ * E_) / 1024, 256>>>(Wq, wqh, wql, E_ * E_);
    split_bf16<<<(E_ * E_) / 1024, 256>>>(Wk, wkh, wkl, E_ * E_);
    split_bf16<<<(E_ * E_) / 1024, 256>>>(Wv, wvh, wvl, E_ * E_);
    split_bf16<<<(E_ * E_) / 1024, 256>>>(Wo, woh, wol, E_ * E_);

    // ---- Q/K/V projections: [4096,1024] = x @ W^T + b ----
    {
        dim3 g(E_ / 128, MTOT / 128, 1);
        gemm_mma<128><<<g, 256>>>(xhi, xlo, wqh, wql, bq, nullptr, qhi, qlo,
                                  E_, E_, E_, E_, 0, 0, 0, 0, 0, 0, 1, 1);
        gemm_mma<128><<<g, 256>>>(xhi, xlo, wkh, wkl, bk, nullptr, khi, klo,
                                  E_, E_, E_, E_, 0, 0, 0, 0, 0, 0, 1, 1);
        gemm_mma<128><<<g, 256>>>(xhi, xlo, wvh, wvl, bv, nullptr, vthi, vtlo,
                                  E_, E_, E_, E_, 0, 0, 0, 0, 0, 0, 1, 2);
    }

    // ---- energy: per (b,h)  S = q @ k^T  (M=N=1024, K=64) ----
    {
        dim3 g(N_ / 128, N_ / 128, BHN);
        gemm_mma<128><<<g, 256>>>(qhi, qlo, khi, klo, nullptr, S, nullptr, nullptr,
                                  D_, E_, E_, N_,
                                  NE, (long)D_,     // A: b, h strides
                                  NE, (long)D_,     // B: b, h strides
                                  HNN, NN,          // C: b, h strides
                                  H_, 0);
    }

    // ---- softmax + /sqrt(E), emit att hi/lo ----
    softmax_rows<<<BHN * N_, 256>>>(S, ahi, alo);

    // ---- ctx: per (b,h)  ctx = att @ v  (M=1024, N=64, K=1024), B = V^T ----
    {
        dim3 g(1, N_ / 128, BHN);
        gemm_mma<64><<<g, 256>>>(ahi, alo, vthi, vtlo, nullptr, nullptr, chi, clo,
                                 N_, N_, N_, E_,
                                 HNN, NN,                           // A(att): b, h
                                 (long)H_ * D_ * N_, (long)D_ * N_, // B(V^T): b, h
                                 NE, (long)D_,                      // C(ctx): b, h
                                 H_, 1);
    }

    // ---- output projection: out = ctx @ Wo^T + bo ----
    {
        dim3 g(E_ / 128, MTOT / 128, 1);
        gemm_mma<128><<<g, 256>>>(chi, clo, woh, wol, bo, out, nullptr, nullptr,
                                  E_, E_, E_, E_, 0, 0, 0, 0, 0, 0, 1, 0);
    }
}

// round 4
// speedup vs baseline: 3.7397x; 1.3296x over previous
#include <cuda_runtime.h>
#include <cuda_bf16.h>
#include <cstdint>
#include <math.h>

// Problem constants
#define B_  4
#define N_  1024
#define E_  1024
#define H_  16
#define D_  64
#define MTOT (B_ * N_)   // 4096
#define BHN  (B_ * H_)   // 64

// ==================== mma.sync / ldmatrix helpers ====================
__device__ __forceinline__ uint32_t smem_to_u32(const void* p) {
    uint32_t a;
    asm("{ .reg .u64 t; cvta.to.shared.u64 t, %1; cvt.u32.u64 %0, t; }" : "=r"(a) : "l"(p));
    return a;
}
#define LDSM_X4(R, ADDR) \
    asm volatile("ldmatrix.sync.aligned.m8n8.x4.shared.b16 {%0,%1,%2,%3}, [%4];" \
        : "=r"((R)[0]), "=r"((R)[1]), "=r"((R)[2]), "=r"((R)[3]) : "r"(ADDR))
#define MMA_BF16(D, A, B0, B1) \
    asm volatile("mma.sync.aligned.m16n8k16.row.col.f32.bf16.bf16.f32 " \
        "{%0,%1,%2,%3}, {%4,%5,%6,%7}, {%8,%9}, {%0,%1,%2,%3};" \
        : "+f"((D)[0]), "+f"((D)[1]), "+f"((D)[2]), "+f"((D)[3]) \
        : "r"((A)[0]), "r"((A)[1]), "r"((A)[2]), "r"((A)[3]), "r"(B0), "r"(B1))

// pack two fp32 -> bf16x2 (lo element in low 16 bits)
__device__ __forceinline__ uint32_t packbf(float lo, float hi) {
    uint32_t d;
    asm("cvt.rn.bf16x2.f32 %0, %1, %2;" : "=r"(d) : "f"(hi), "f"(lo));
    return d;
}
__device__ __forceinline__ float tobf(float v) {
    return __bfloat162float(__float2bfloat16(v));
}

// ==================== scratch (device globals) ====================
__device__ __nv_bfloat16 g_xhi[MTOT * E_], g_xlo[MTOT * E_];
__device__ __nv_bfloat16 g_wqh[E_ * E_], g_wql[E_ * E_];
__device__ __nv_bfloat16 g_wkh[E_ * E_], g_wkl[E_ * E_];
__device__ __nv_bfloat16 g_wvh[E_ * E_], g_wvl[E_ * E_];
__device__ __nv_bfloat16 g_woh[E_ * E_], g_wol[E_ * E_];
__device__ __nv_bfloat16 g_qhi[MTOT * E_], g_qlo[MTOT * E_];
__device__ __nv_bfloat16 g_khi[MTOT * E_], g_klo[MTOT * E_];
__device__ __nv_bfloat16 g_vthi[BHN * D_ * N_], g_vtlo[BHN * D_ * N_];  // V^T: [bh][d][tok]
__device__ __nv_bfloat16 g_chi[MTOT * E_], g_clo[MTOT * E_];

// ==================== fp32 -> bf16 hi/lo split ====================
__global__ __launch_bounds__(256)
void split_bf16(const float* __restrict__ in, __nv_bfloat16* __restrict__ hi,
                __nv_bfloat16* __restrict__ lo, int n)
{
    int i = (blockIdx.x * 256 + threadIdx.x) * 4;
    if (i >= n) return;
    float4 v = *reinterpret_cast<const float4*>(in + i);
    float vv[4] = {v.x, v.y, v.z, v.w};
    #pragma unroll
    for (int j = 0; j < 4; j++) {
        __nv_bfloat16 h = __float2bfloat16(vv[j]);
        float r = vv[j] - __bfloat162float(h);
        hi[i + j] = h;
        lo[i + j] = __float2bfloat16(r);
    }
}

// ==================== split-bf16 warp-tiled mma.sync GEMM (projections) ====================
// C[M,N] = (Ah+Al)[M,K] @ (Bh+Bl)[N,K]^T (+bias).  K-major operands.
// BM=128, BN=128, BK=32. 256 threads = 8 warps (4 M x 2 N).
// mode: 0 = fp32 store, 1 = bf16 hi/lo store, 2 = V-transpose bf16 hi/lo store
__global__ void __launch_bounds__(256)
gemm_mma(const __nv_bfloat16* __restrict__ Ah, const __nv_bfloat16* __restrict__ Al,
         const __nv_bfloat16* __restrict__ Bh, const __nv_bfloat16* __restrict__ Bl,
         const float* __restrict__ bias,
         float* __restrict__ Cf, __nv_bfloat16* __restrict__ Chi, __nv_bfloat16* __restrict__ Clo,
         int K, int lda, int ldb, int ldc, int mode)
{
    constexpr int BN_ = 128;
    constexpr int WN  = 64;
    constexpr int NFR = 8;
    constexpr int STR = 80;
    constexpr int SA_HI = 0;
    constexpr int SA_LO = 128 * STR;
    constexpr int SB_HI = 2 * 128 * STR;
    constexpr int SB_LO = SB_HI + BN_ * STR;

    __shared__ char smem[SB_HI + 2 * BN_ * STR];
    const uint32_t sbase = smem_to_u32(smem);

    const int tid  = threadIdx.x;
    const int warp = tid >> 5;
    const int lane = tid & 31;
    const int wm = warp & 3;
    const int wn = warp >> 2;

    const int row0 = blockIdx.y * 128;
    const int col0 = blockIdx.x * BN_;

    const int lrow = (lane & 7) | (((lane >> 3) & 1) << 3);
    const int lk8b = (lane >> 4) * 16;

    float acc[2][NFR][4];
    #pragma unroll
    for (int mi = 0; mi < 2; mi++)
        #pragma unroll
        for (int nj = 0; nj < NFR; nj++)
            #pragma unroll
            for (int r = 0; r < 4; r++) acc[mi][nj][r] = 0.f;

    const int nch = K >> 5;
    for (int kc = 0; kc < nch; kc++) {
        const __nv_bfloat16* pAh = Ah + (long)row0 * lda + kc * 32;
        const __nv_bfloat16* pAl = Al + (long)row0 * lda + kc * 32;
        #pragma unroll
        for (int i = 0; i < 2; i++) {
            int c = tid + i * 256;
            int r = c >> 2, k8 = c & 3;
            uint32_t so = r * STR + k8 * 16;
            *reinterpret_cast<uint4*>(smem + SA_HI + so) =
                *reinterpret_cast<const uint4*>(pAh + (long)r * lda + k8 * 8);
            *reinterpret_cast<uint4*>(smem + SA_LO + so) =
                *reinterpret_cast<const uint4*>(pAl + (long)r * lda + k8 * 8);
        }
        const __nv_bfloat16* pBh = Bh + (long)col0 * ldb + kc * 32;
        const __nv_bfloat16* pBl = Bl + (long)col0 * ldb + kc * 32;
        #pragma unroll
        for (int i = 0; i < 2; i++) {
            int c = tid + i * 256;
            int r = c >> 2, k8 = c & 3;
            uint32_t so = r * STR + k8 * 16;
            *reinterpret_cast<uint4*>(smem + SB_HI + so) =
                *reinterpret_cast<const uint4*>(pBh + (long)r * ldb + k8 * 8);
            *reinterpret_cast<uint4*>(smem + SB_LO + so) =
                *reinterpret_cast<const uint4*>(pBl + (long)r * ldb + k8 * 8);
        }
        __syncthreads();

        #pragma unroll
        for (int ks = 0; ks < 2; ks++) {
            uint32_t aH[2][4], aL[2][4];
            #pragma unroll
            for (int mi = 0; mi < 2; mi++) {
                uint32_t ao = sbase + SA_HI
                            + (uint32_t)(wm * 32 + mi * 16 + lrow) * STR + ks * 32 + lk8b;
                LDSM_X4(aH[mi], ao);
                LDSM_X4(aL[mi], ao + (SA_LO - SA_HI));
            }
            #pragma unroll
            for (int nj = 0; nj < NFR / 2; nj++) {
                uint32_t bo = sbase + SB_HI
                            + (uint32_t)(wn * WN + nj * 16 + lrow) * STR + ks * 32 + lk8b;
                uint32_t bH[4], bL[4];
                LDSM_X4(bH, bo);
                LDSM_X4(bL, bo + (uint32_t)(BN_ * STR));
                #pragma unroll
                for (int mi = 0; mi < 2; mi++) {
                    MMA_BF16(acc[mi][2 * nj],     aH[mi], bH[0], bH[2]);
                    MMA_BF16(acc[mi][2 * nj],     aH[mi], bL[0], bL[2]);
                    MMA_BF16(acc[mi][2 * nj],     aL[mi], bH[0], bH[2]);
                    MMA_BF16(acc[mi][2 * nj + 1], aH[mi], bH[1], bH[3]);
                    MMA_BF16(acc[mi][2 * nj + 1], aH[mi], bL[1], bL[3]);
                    MMA_BF16(acc[mi][2 * nj + 1], aL[mi], bH[1], bH[3]);
                }
            }
        }
        __syncthreads();
    }

    #pragma unroll
    for (int mi = 0; mi < 2; mi++) {
        int rg = row0 + wm * 32 + mi * 16 + (lane >> 2);
        #pragma unroll
        for (int nj = 0; nj < NFR; nj++) {
            int cg = col0 + wn * WN + nj * 8 + (lane & 3) * 2;
            #pragma unroll
            for (int rr = 0; rr < 2; rr++) {
                int m = rg + rr * 8;
                #pragma unroll
                for (int cc = 0; cc < 2; cc++) {
                    int col = cg + cc;
                    float v = acc[mi][nj][rr * 2 + cc];
                    if (bias) v += bias[col];
                    if (mode == 0) {
                        Cf[(long)m * ldc + col] = v;
                    } else if (mode == 1) {
                        __nv_bfloat16 h = __float2bfloat16(v);
                        float r = v - __bfloat162float(h);
                        long o = (long)m * ldc + col;
                        Chi[o] = h;
                        Clo[o] = __float2bfloat16(r);
                    } else {
                        // V^T store: row m = b*1024+tok, col = h*64+d -> [b*H+h][d][tok]
                        int hh = col >> 6, dc = col & 63;
                        int b = m >> 10, tok = m & 1023;
                        long o = ((long)(b * H_ + hh) * D_ + dc) * N_ + tok;
                        __nv_bfloat16 h = __float2bfloat16(v);
                        float r = v - __bfloat162float(h);
                        Chi[o] = h;
                        Clo[o] = __float2bfloat16(r);
                    }
                }
            }
        }
    }
}

// ==================== fused flash attention ====================
// Per CTA: one (Q-tile of 128 rows) x one (b,h). 256 threads = 8 warps,
// each warp owns 16 Q rows (full M split -> softmax stats intra-warp only).
// Loop over 8 KV chunks of 128 tokens: split-bf16 energy MMA -> online
// softmax in registers -> pack P to bf16 hi/lo A-frags -> split AV MMA.
// Epilogue: O / (l * 32), store ctx as bf16 hi/lo [b*1024+tok][h*64+d].
#define STRK 144
#define STRV 272
#define OFF_KHI 0
#define OFF_KLO (128 * STRK)               // 18432
#define OFF_VHI (2 * 128 * STRK)           // 36864
#define OFF_VLO (OFF_VHI + 64 * STRV)      // 54272
#define SMEM_FLASH (OFF_VLO + 64 * STRV)   // 71680

__global__ void __launch_bounds__(256, 1)
flash_attn(const __nv_bfloat16* __restrict__ qhi, const __nv_bfloat16* __restrict__ qlo,
           const __nv_bfloat16* __restrict__ khi, const __nv_bfloat16* __restrict__ klo,
           const __nv_bfloat16* __restrict__ vthi, const __nv_bfloat16* __restrict__ vtlo,
           __nv_bfloat16* __restrict__ chi, __nv_bfloat16* __restrict__ clo)
{
    extern __shared__ char smem[];
    const uint32_t sbase = smem_to_u32(smem);
    const int tid = threadIdx.x, warp = tid >> 5, lane = tid & 31;
    const int bh = blockIdx.y, b = bh >> 4, h = bh & 15;
    const int q0 = blockIdx.x * 128;

    const __nv_bfloat16* Qh = qhi + (long)(b * 1024 + q0) * 1024 + h * 64;
    const __nv_bfloat16* Ql = qlo + (long)(b * 1024 + q0) * 1024 + h * 64;
    const __nv_bfloat16* Kh = khi + (long)(b * 1024) * 1024 + h * 64;
    const __nv_bfloat16* Kl = klo + (long)(b * 1024) * 1024 + h * 64;
    const __nv_bfloat16* Vh = vthi + (long)bh * D_ * N_;
    const __nv_bfloat16* Vl = vtlo + (long)bh * D_ * N_;

    const int lrow = (lane & 7) | (((lane >> 3) & 1) << 3);
    const int lk8b = (lane >> 4) * 16;

    // ---- stage Q tile through smem, load Q fragments to registers ----
    #pragma unroll
    for (int i = 0; i < 4; i++) {
        int idx = tid + i * 256;           // 0..1023
        int r = idx >> 3, c8 = idx & 7;    // 128 rows x 8 x 16B
        *reinterpret_cast<uint4*>(smem + OFF_KHI + r * STRK + c8 * 16) =
            *reinterpret_cast<const uint4*>(Qh + (long)r * 1024 + c8 * 8);
        *reinterpret_cast<uint4*>(smem + OFF_KLO + r * STRK + c8 * 16) =
            *reinterpret_cast<const uint4*>(Ql + (long)r * 1024 + c8 * 8);
    }
    __syncthreads();
    uint32_t qh[4][4], ql[4][4];
    #pragma unroll
    for (int ks = 0; ks < 4; ks++) {
        uint32_t ao = sbase + OFF_KHI + (uint32_t)(warp * 16 + lrow) * STRK + ks * 32 + lk8b;
        LDSM_X4(qh[ks], ao);
        LDSM_X4(ql[ks], ao + OFF_KLO);
    }

    float m0 = -INFINITY, m1 = -INFINITY;
    float l0 = 0.f, l1 = 0.f;
    float o[8][4];
    #pragma unroll
    for (int nf = 0; nf < 8; nf++)
        #pragma unroll
        for (int r = 0; r < 4; r++) o[nf][r] = 0.f;

    for (int t = 0; t < 8; t++) {
        const int tok0 = t * 128;
        __syncthreads();   // previous compute (and Q frag loads) done before overwrite
        // ---- load K chunk (128 tok x 64 d) hi/lo ----
        #pragma unroll
        for (int i = 0; i < 4; i++) {
            int idx = tid + i * 256;
            int r = idx >> 3, c8 = idx & 7;
            *reinterpret_cast<uint4*>(smem + OFF_KHI + r * STRK + c8 * 16) =
                *reinterpret_cast<const uint4*>(Kh + (long)(tok0 + r) * 1024 + c8 * 8);
            *reinterpret_cast<uint4*>(smem + OFF_KLO + r * STRK + c8 * 16) =
                *reinterpret_cast<const uint4*>(Kl + (long)(tok0 + r) * 1024 + c8 * 8);
        }
        // ---- load V^T chunk (64 d x 128 tok) hi/lo ----
        #pragma unroll
        for (int i = 0; i < 4; i++) {
            int idx = tid + i * 256;
            int r = idx >> 4, c = idx & 15;
            *reinterpret_cast<uint4*>(smem + OFF_VHI + r * STRV + c * 16) =
                *reinterpret_cast<const uint4*>(Vh + (long)r * N_ + tok0 + c * 8);
            *reinterpret_cast<uint4*>(smem + OFF_VLO + r * STRV + c * 16) =
                *reinterpret_cast<const uint4*>(Vl + (long)r * N_ + tok0 + c * 8);
        }
        __syncthreads();

        // ---- energy: S[16 rows][128 tok] per warp ----
        float s[16][4];
        #pragma unroll
        for (int nf = 0; nf < 16; nf++)
            #pragma unroll
            for (int r = 0; r < 4; r++) s[nf][r] = 0.f;

        #pragma unroll
        for (int ks = 0; ks < 4; ks++) {
            #pragma unroll
            for (int nf2 = 0; nf2 < 8; nf2++) {
                uint32_t bo = sbase + OFF_KHI + (uint32_t)(nf2 * 16 + lrow) * STRK + ks * 32 + lk8b;
                uint32_t bH[4], bL[4];
                LDSM_X4(bH, bo);
                LDSM_X4(bL, bo + OFF_KLO);
                MMA_BF16(s[2 * nf2],     qh[ks], bH[0], bH[2]);
                MMA_BF16(s[2 * nf2],     qh[ks], bL[0], bL[2]);
                MMA_BF16(s[2 * nf2],     ql[ks], bH[0], bH[2]);
                MMA_BF16(s[2 * nf2 + 1], qh[ks], bH[1], bH[3]);
                MMA_BF16(s[2 * nf2 + 1], qh[ks], bL[1], bL[3]);
                MMA_BF16(s[2 * nf2 + 1], ql[ks], bH[1], bH[3]);
            }
        }

        // ---- online softmax (rows r = lane>>2 and r+8, stats intra-quad) ----
        float mx0 = -INFINITY, mx1 = -INFINITY;
        #pragma unroll
        for (int nf = 0; nf < 16; nf++) {
            mx0 = fmaxf(mx0, fmaxf(s[nf][0], s[nf][1]));
            mx1 = fmaxf(mx1, fmaxf(s[nf][2], s[nf][3]));
        }
        mx0 = fmaxf(mx0, __shfl_xor_sync(0xffffffffu, mx0, 1));
        mx0 = fmaxf(mx0, __shfl_xor_sync(0xffffffffu, mx0, 2));
        mx1 = fmaxf(mx1, __shfl_xor_sync(0xffffffffu, mx1, 1));
        mx1 = fmaxf(mx1, __shfl_xor_sync(0xffffffffu, mx1, 2));
        const float mn0 = fmaxf(m0, mx0), mn1 = fmaxf(m1, mx1);
        const float sc0 = __expf(m0 - mn0), sc1 = __expf(m1 - mn1);
        m0 = mn0; m1 = mn1;

        float sum0 = 0.f, sum1 = 0.f;
        #pragma unroll
        for (int nf = 0; nf < 16; nf++) {
            s[nf][0] = __expf(s[nf][0] - mn0);
            s[nf][1] = __expf(s[nf][1] - mn0);
            s[nf][2] = __expf(s[nf][2] - mn1);
            s[nf][3] = __expf(s[nf][3] - mn1);
            sum0 += s[nf][0] + s[nf][1];
            sum1 += s[nf][2] + s[nf][3];
        }
        sum0 += __shfl_xor_sync(0xffffffffu, sum0, 1);
        sum0 += __shfl_xor_sync(0xffffffffu, sum0, 2);
        sum1 += __shfl_xor_sync(0xffffffffu, sum1, 1);
        sum1 += __shfl_xor_sync(0xffffffffu, sum1, 2);
        l0 = l0 * sc0 + sum0;
        l1 = l1 * sc1 + sum1;
        #pragma unroll
        for (int nf = 0; nf < 8; nf++) {
            o[nf][0] *= sc0; o[nf][1] *= sc0;
            o[nf][2] *= sc1; o[nf][3] *= sc1;
        }

        // ---- AV: O[16 rows][64 d] += P @ V^T  (P frags from S regs) ----
        #pragma unroll
        for (int kv = 0; kv < 8; kv++) {
            const float* f0 = s[2 * kv];
            const float* f1 = s[2 * kv + 1];
            uint32_t aH[4], aL[4];
            aH[0] = packbf(f0[0], f0[1]);
            aH[1] = packbf(f0[2], f0[3]);
            aH[2] = packbf(f1[0], f1[1]);
            aH[3] = packbf(f1[2], f1[3]);
            aL[0] = packbf(f0[0] - tobf(f0[0]), f0[1] - tobf(f0[1]));
            aL[1] = packbf(f0[2] - tobf(f0[2]), f0[3] - tobf(f0[3]));
            aL[2] = packbf(f1[0] - tobf(f1[0]), f1[1] - tobf(f1[1]));
            aL[3] = packbf(f1[2] - tobf(f1[2]), f1[3] - tobf(f1[3]));
            #pragma unroll
            for (int nd2 = 0; nd2 < 4; nd2++) {
                uint32_t vo = sbase + OFF_VHI + (uint32_t)(nd2 * 16 + lrow) * STRV + kv * 32 + lk8b;
                uint32_t vH[4], vL[4];
                LDSM_X4(vH, vo);
                LDSM_X4(vL, vo + (OFF_VLO - OFF_VHI));
                MMA_BF16(o[2 * nd2],     aH, vH[0], vH[2]);
                MMA_BF16(o[2 * nd2],     aL, vH[0], vH[2]);
                MMA_BF16(o[2 * nd2],     aH, vL[0], vL[2]);
                MMA_BF16(o[2 * nd2 + 1], aH, vH[1], vH[3]);
                MMA_BF16(o[2 * nd2 + 1], aL, vH[1], vH[3]);
                MMA_BF16(o[2 * nd2 + 1], aH, vL[1], vL[3]);
            }
        }
    }

    // ---- epilogue: normalize by 1/(l * sqrt(E)), store ctx hi/lo ----
    const float inv0 = 1.0f / (l0 * 32.0f);
    const float inv1 = 1.0f / (l1 * 32.0f);
    const int gr = b * 1024 + q0 + warp * 16 + (lane >> 2);
    const int colb = h * 64 + (lane & 3) * 2;
    #pragma unroll
    for (int nf = 0; nf < 8; nf++) {
        int col = colb + nf * 8;
        float v0 = o[nf][0] * inv0, v1 = o[nf][1] * inv0;
        float v2 = o[nf][2] * inv1, v3 = o[nf][3] * inv1;
        long o0 = (long)gr * 1024 + col;
        long o8 = (long)(gr + 8) * 1024 + col;
        *reinterpret_cast<uint32_t*>(chi + o0) = packbf(v0, v1);
        *reinterpret_cast<uint32_t*>(clo + o0) = packbf(v0 - tobf(v0), v1 - tobf(v1));
        *reinterpret_cast<uint32_t*>(chi + o8) = packbf(v2, v3);
        *reinterpret_cast<uint32_t*>(clo + o8) = packbf(v2 - tobf(v2), v3 - tobf(v3));
    }
}

// ==================== launch ====================
extern "C" void kernel_launch(void* const* d_in, const int* in_sizes, int n_in,
                              void* d_out, int out_size)
{
    const float* x  = (const float*)d_in[0];
    const float* Wq = (const float*)d_in[1];
    const float* bq = (const float*)d_in[2];
    const float* Wk = (const float*)d_in[3];
    const float* bk = (const float*)d_in[4];
    const float* Wv = (const float*)d_in[5];
    const float* bv = (const float*)d_in[6];
    const float* Wo = (const float*)d_in[7];
    const float* bo = (const float*)d_in[8];
    float* out = (float*)d_out;

    __nv_bfloat16 *xhi, *xlo, *wqh, *wql, *wkh, *wkl, *wvh, *wvl, *woh, *wol;
    __nv_bfloat16 *qhi, *qlo, *khi, *klo, *vthi, *vtlo, *chi, *clo;
    cudaGetSymbolAddress((void**)&xhi, g_xhi);   cudaGetSymbolAddress((void**)&xlo, g_xlo);
    cudaGetSymbolAddress((void**)&wqh, g_wqh);   cudaGetSymbolAddress((void**)&wql, g_wql);
    cudaGetSymbolAddress((void**)&wkh, g_wkh);   cudaGetSymbolAddress((void**)&wkl, g_wkl);
    cudaGetSymbolAddress((void**)&wvh, g_wvh);   cudaGetSymbolAddress((void**)&wvl, g_wvl);
    cudaGetSymbolAddress((void**)&woh, g_woh);   cudaGetSymbolAddress((void**)&wol, g_wol);
    cudaGetSymbolAddress((void**)&qhi, g_qhi);   cudaGetSymbolAddress((void**)&qlo, g_qlo);
    cudaGetSymbolAddress((void**)&khi, g_khi);   cudaGetSymbolAddress((void**)&klo, g_klo);
    cudaGetSymbolAddress((void**)&vthi, g_vthi); cudaGetSymbolAddress((void**)&vtlo, g_vtlo);
    cudaGetSymbolAddress((void**)&chi, g_chi);   cudaGetSymbolAddress((void**)&clo, g_clo);

    cudaFuncSetAttribute(flash_attn, cudaFuncAttributeMaxDynamicSharedMemorySize, SMEM_FLASH);

    // ---- split inputs/weights to bf16 hi/lo ----
    split_bf16<<<(MTOT * E_) / 1024, 256>>>(x, xhi, xlo, MTOT * E_);
    split_bf16<<<(E_ * E_) / 1024, 256>>>(Wq, wqh, wql, E_ * E_);
    split_bf16<<<(E_ * E_) / 1024, 256>>>(Wk, wkh, wkl, E_ * E_);
    split_bf16<<<(E_ * E_) / 1024, 256>>>(Wv, wvh, wvl, E_ * E_);
    split_bf16<<<(E_ * E_) / 1024, 256>>>(Wo, woh, wol, E_ * E_);

    // ---- Q/K/V projections ----
    {
        dim3 g(E_ / 128, MTOT / 128);
        gemm_mma<<<g, 256>>>(xhi, xlo, wqh, wql, bq, nullptr, qhi, qlo, E_, E_, E_, E_, 1);
        gemm_mma<<<g, 256>>>(xhi, xlo, wkh, wkl, bk, nullptr, khi, klo, E_, E_, E_, E_, 1);
        gemm_mma<<<g, 256>>>(xhi, xlo, wvh, wvl, bv, nullptr, vthi, vtlo, E_, E_, E_, E_, 2);
    }

    // ---- fused attention: energy -> softmax(/32 after) -> AV ----
    {
        dim3 g(N_ / 128, BHN);
        flash_attn<<<g, 256, SMEM_FLASH>>>(qhi, qlo, khi, klo, vthi, vtlo, chi, clo);
    }

    // ---- output projection: out = ctx @ Wo^T + bo ----
    {
        dim3 g(E_ / 128, MTOT / 128);
        gemm_mma<<<g, 256>>>(chi, clo, woh, wol, bo, out, nullptr, nullptr, E_, E_, E_, E_, 0);
    }
}

// round 5
// speedup vs baseline: 4.8443x; 1.2954x over previous
#include <cuda_runtime.h>
#include <cuda_bf16.h>
#include <cstdint>
#include <math.h>

// Problem constants
#define B_  4
#define N_  1024
#define E_  1024
#define H_  16
#define D_  64
#define MTOT (B_ * N_)   // 4096
#define BHN  (B_ * H_)   // 64

// ==================== mma.sync / ldmatrix / cp.async helpers ====================
__device__ __forceinline__ uint32_t smem_to_u32(const void* p) {
    uint32_t a;
    asm("{ .reg .u64 t; cvta.to.shared.u64 t, %1; cvt.u32.u64 %0, t; }" : "=r"(a) : "l"(p));
    return a;
}
#define LDSM_X4(R, ADDR) \
    asm volatile("ldmatrix.sync.aligned.m8n8.x4.shared.b16 {%0,%1,%2,%3}, [%4];" \
        : "=r"((R)[0]), "=r"((R)[1]), "=r"((R)[2]), "=r"((R)[3]) : "r"(ADDR))
#define MMA_BF16(D, A, B0, B1) \
    asm volatile("mma.sync.aligned.m16n8k16.row.col.f32.bf16.bf16.f32 " \
        "{%0,%1,%2,%3}, {%4,%5,%6,%7}, {%8,%9}, {%0,%1,%2,%3};" \
        : "+f"((D)[0]), "+f"((D)[1]), "+f"((D)[2]), "+f"((D)[3]) \
        : "r"((A)[0]), "r"((A)[1]), "r"((A)[2]), "r"((A)[3]), "r"(B0), "r"(B1))
#define CP_A16(DST, SRC) \
    asm volatile("cp.async.ca.shared.global [%0], [%1], 16;" :: "r"(DST), "l"(SRC))
#define CP_COMMIT() asm volatile("cp.async.commit_group;" ::: "memory")
#define CP_WAIT0()  asm volatile("cp.async.wait_group 0;" ::: "memory")

__device__ __forceinline__ uint32_t packbf(float lo, float hi) {
    uint32_t d;
    asm("cvt.rn.bf16x2.f32 %0, %1, %2;" : "=r"(d) : "f"(hi), "f"(lo));
    return d;
}
__device__ __forceinline__ float tobf(float v) {
    return __bfloat162float(__float2bfloat16(v));
}

// ==================== scratch (device globals) ====================
__device__ __nv_bfloat16 g_xhi[MTOT * E_], g_xlo[MTOT * E_];
__device__ __nv_bfloat16 g_wqh[E_ * E_], g_wql[E_ * E_];
__device__ __nv_bfloat16 g_wkh[E_ * E_], g_wkl[E_ * E_];
__device__ __nv_bfloat16 g_wvh[E_ * E_], g_wvl[E_ * E_];
__device__ __nv_bfloat16 g_woh[E_ * E_], g_wol[E_ * E_];
__device__ __nv_bfloat16 g_qhi[MTOT * E_], g_qlo[MTOT * E_];
__device__ __nv_bfloat16 g_khi[MTOT * E_], g_klo[MTOT * E_];
__device__ __nv_bfloat16 g_vthi[BHN * D_ * N_], g_vtlo[BHN * D_ * N_];  // V^T: [bh][d][tok]
__device__ __nv_bfloat16 g_chi[MTOT * E_], g_clo[MTOT * E_];

// ==================== fp32 -> bf16 hi/lo split ====================
__global__ __launch_bounds__(256)
void split_bf16(const float* __restrict__ in, __nv_bfloat16* __restrict__ hi,
                __nv_bfloat16* __restrict__ lo, int n)
{
    int i = (blockIdx.x * 256 + threadIdx.x) * 4;
    if (i >= n) return;
    float4 v = *reinterpret_cast<const float4*>(in + i);
    float vv[4] = {v.x, v.y, v.z, v.w};
    #pragma unroll
    for (int j = 0; j < 4; j++) {
        __nv_bfloat16 h = __float2bfloat16(vv[j]);
        float r = vv[j] - __bfloat162float(h);
        hi[i + j] = h;
        lo[i + j] = __float2bfloat16(r);
    }
}

// ==================== pipelined split-bf16 GEMM core ====================
// Tile: BM=128, BN=128, BK=32. 256 threads = 8 warps (4M x 2N).
// 2-stage cp.async pipeline. Smem per stage: A hi/lo + B hi/lo, STR=80B rows.
#define GSTR   80
#define G_ALO  10240
#define G_BHI  20480
#define G_BLO  30720
#define GSTAGE 40960
#define GSMEM  (2 * GSTAGE)

struct GemmAcc { float a[2][8][4]; };

__device__ __forceinline__ void gemm_issue(char* smem, int stg,
    const __nv_bfloat16* pAh, const __nv_bfloat16* pAl,
    const __nv_bfloat16* pBh, const __nv_bfloat16* pBl,
    int lda, int ldb, int tid, uint32_t sbase)
{
    const uint32_t so0 = sbase + stg * GSTAGE;
    #pragma unroll
    for (int i = 0; i < 2; i++) {
        int c = tid + i * 256;
        int r = c >> 2, k8 = c & 3;
        uint32_t so = r * GSTR + k8 * 16;
        CP_A16(so0 + so,          pAh + (long)r * lda + k8 * 8);
        CP_A16(so0 + G_ALO + so,  pAl + (long)r * lda + k8 * 8);
        CP_A16(so0 + G_BHI + so,  pBh + (long)r * ldb + k8 * 8);
        CP_A16(so0 + G_BLO + so,  pBl + (long)r * ldb + k8 * 8);
    }
}

__device__ __forceinline__ void gemm_compute(uint32_t sbase, int stg, GemmAcc& acc,
                                             int wm, int wn, int lrow, int lk8b)
{
    const uint32_t s0 = sbase + stg * GSTAGE;
    #pragma unroll
    for (int ks = 0; ks < 2; ks++) {
        uint32_t aH[2][4], aL[2][4];
        #pragma unroll
        for (int mi = 0; mi < 2; mi++) {
            uint32_t ao = s0 + (uint32_t)(wm * 32 + mi * 16 + lrow) * GSTR + ks * 32 + lk8b;
            LDSM_X4(aH[mi], ao);
            LDSM_X4(aL[mi], ao + G_ALO);
        }
        #pragma unroll
        for (int nj = 0; nj < 4; nj++) {
            uint32_t bo = s0 + G_BHI + (uint32_t)(wn * 64 + nj * 16 + lrow) * GSTR + ks * 32 + lk8b;
            uint32_t bH[4], bL[4];
            LDSM_X4(bH, bo);
            LDSM_X4(bL, bo + (G_BLO - G_BHI));
            #pragma unroll
            for (int mi = 0; mi < 2; mi++) {
                MMA_BF16(acc.a[mi][2 * nj],     aH[mi], bH[0], bH[2]);
                MMA_BF16(acc.a[mi][2 * nj],     aH[mi], bL[0], bL[2]);
                MMA_BF16(acc.a[mi][2 * nj],     aL[mi], bH[0], bH[2]);
                MMA_BF16(acc.a[mi][2 * nj + 1], aH[mi], bH[1], bH[3]);
                MMA_BF16(acc.a[mi][2 * nj + 1], aH[mi], bL[1], bL[3]);
                MMA_BF16(acc.a[mi][2 * nj + 1], aL[mi], bH[1], bH[3]);
            }
        }
    }
}

// ---- merged QKV projection: logical C[4096, 3072], weight picked per CTA ----
__global__ void __launch_bounds__(256)
gemm_qkv(const __nv_bfloat16* __restrict__ Ah, const __nv_bfloat16* __restrict__ Al,
         const __nv_bfloat16* __restrict__ wqh, const __nv_bfloat16* __restrict__ wql,
         const __nv_bfloat16* __restrict__ wkh, const __nv_bfloat16* __restrict__ wkl,
         const __nv_bfloat16* __restrict__ wvh, const __nv_bfloat16* __restrict__ wvl,
         const float* __restrict__ bq, const float* __restrict__ bk, const float* __restrict__ bv,
         __nv_bfloat16* __restrict__ qhi, __nv_bfloat16* __restrict__ qlo,
         __nv_bfloat16* __restrict__ khi, __nv_bfloat16* __restrict__ klo,
         __nv_bfloat16* __restrict__ vthi, __nv_bfloat16* __restrict__ vtlo)
{
    extern __shared__ char smem[];
    const uint32_t sbase = smem_to_u32(smem);
    const int tid = threadIdx.x, warp = tid >> 5, lane = tid & 31;
    const int wm = warp & 3, wn = warp >> 2;
    const int lrow = (lane & 7) | (((lane >> 3) & 1) << 3);
    const int lk8b = (lane >> 4) * 16;

    const int widx = blockIdx.x >> 3;          // 0=Q, 1=K, 2=V
    const int col0 = (blockIdx.x & 7) * 128;   // within-weight column tile
    const int row0 = blockIdx.y * 128;

    const __nv_bfloat16* Bh = (widx == 0) ? wqh : (widx == 1) ? wkh : wvh;
    const __nv_bfloat16* Bl = (widx == 0) ? wql : (widx == 1) ? wkl : wvl;
    const float* bias = (widx == 0) ? bq : (widx == 1) ? bk : bv;

    GemmAcc acc;
    #pragma unroll
    for (int mi = 0; mi < 2; mi++)
        #pragma unroll
        for (int nj = 0; nj < 8; nj++)
            #pragma unroll
            for (int r = 0; r < 4; r++) acc.a[mi][nj][r] = 0.f;

    const int nch = E_ >> 5;  // 32
    gemm_issue(smem, 0, Ah + (long)row0 * E_, Al + (long)row0 * E_,
               Bh + (long)col0 * E_, Bl + (long)col0 * E_, E_, E_, tid, sbase);
    CP_COMMIT();
    CP_WAIT0();
    __syncthreads();

    for (int kc = 0; kc < nch; kc++) {
        if (kc + 1 < nch) {
            gemm_issue(smem, (kc + 1) & 1,
                       Ah + (long)row0 * E_ + (kc + 1) * 32, Al + (long)row0 * E_ + (kc + 1) * 32,
                       Bh + (long)col0 * E_ + (kc + 1) * 32, Bl + (long)col0 * E_ + (kc + 1) * 32,
                       E_, E_, tid, sbase);
            CP_COMMIT();
        }
        gemm_compute(sbase, kc & 1, acc, wm, wn, lrow, lk8b);
        if (kc + 1 < nch) { CP_WAIT0(); __syncthreads(); }
    }

    // epilogue
    #pragma unroll
    for (int mi = 0; mi < 2; mi++) {
        int rg = row0 + wm * 32 + mi * 16 + (lane >> 2);
        #pragma unroll
        for (int nj = 0; nj < 8; nj++) {
            int cg = col0 + wn * 64 + nj * 8 + (lane & 3) * 2;
            #pragma unroll
            for (int rr = 0; rr < 2; rr++) {
                int m = rg + rr * 8;
                #pragma unroll
                for (int cc = 0; cc < 2; cc++) {
                    int col = cg + cc;
                    float v = acc.a[mi][nj][rr * 2 + cc] + bias[col];
                    __nv_bfloat16 h = __float2bfloat16(v);
                    __nv_bfloat16 r = __float2bfloat16(v - __bfloat162float(h));
                    if (widx == 0) {
                        long o = (long)m * E_ + col;
                        qhi[o] = h; qlo[o] = r;
                    } else if (widx == 1) {
                        long o = (long)m * E_ + col;
                        khi[o] = h; klo[o] = r;
                    } else {
                        int hh = col >> 6, dc = col & 63;
                        int b = m >> 10, tok = m & 1023;
                        long o = ((long)(b * H_ + hh) * D_ + dc) * N_ + tok;
                        vthi[o] = h; vtlo[o] = r;
                    }
                }
            }
        }
    }
}

// ---- output projection: out(fp32) = ctx @ Wo^T + bo ----
__global__ void __launch_bounds__(256)
gemm_out(const __nv_bfloat16* __restrict__ Ah, const __nv_bfloat16* __restrict__ Al,
         const __nv_bfloat16* __restrict__ Bh, const __nv_bfloat16* __restrict__ Bl,
         const float* __restrict__ bias, float* __restrict__ Cf)
{
    extern __shared__ char smem[];
    const uint32_t sbase = smem_to_u32(smem);
    const int tid = threadIdx.x, warp = tid >> 5, lane = tid & 31;
    const int wm = warp & 3, wn = warp >> 2;
    const int lrow = (lane & 7) | (((lane >> 3) & 1) << 3);
    const int lk8b = (lane >> 4) * 16;

    const int col0 = blockIdx.x * 128;
    const int row0 = blockIdx.y * 128;

    GemmAcc acc;
    #pragma unroll
    for (int mi = 0; mi < 2; mi++)
        #pragma unroll
        for (int nj = 0; nj < 8; nj++)
            #pragma unroll
            for (int r = 0; r < 4; r++) acc.a[mi][nj][r] = 0.f;

    const int nch = E_ >> 5;
    gemm_issue(smem, 0, Ah + (long)row0 * E_, Al + (long)row0 * E_,
               Bh + (long)col0 * E_, Bl + (long)col0 * E_, E_, E_, tid, sbase);
    CP_COMMIT();
    CP_WAIT0();
    __syncthreads();

    for (int kc = 0; kc < nch; kc++) {
        if (kc + 1 < nch) {
            gemm_issue(smem, (kc + 1) & 1,
                       Ah + (long)row0 * E_ + (kc + 1) * 32, Al + (long)row0 * E_ + (kc + 1) * 32,
                       Bh + (long)col0 * E_ + (kc + 1) * 32, Bl + (long)col0 * E_ + (kc + 1) * 32,
                       E_, E_, tid, sbase);
            CP_COMMIT();
        }
        gemm_compute(sbase, kc & 1, acc, wm, wn, lrow, lk8b);
        if (kc + 1 < nch) { CP_WAIT0(); __syncthreads(); }
    }

    #pragma unroll
    for (int mi = 0; mi < 2; mi++) {
        int rg = row0 + wm * 32 + mi * 16 + (lane >> 2);
        #pragma unroll
        for (int nj = 0; nj < 8; nj++) {
            int cg = col0 + wn * 64 + nj * 8 + (lane & 3) * 2;
            #pragma unroll
            for (int rr = 0; rr < 2; rr++) {
                int m = rg + rr * 8;
                #pragma unroll
                for (int cc = 0; cc < 2; cc++) {
                    int col = cg + cc;
                    Cf[(long)m * E_ + col] = acc.a[mi][nj][rr * 2 + cc] + bias[col];
                }
            }
        }
    }
}

// ==================== fused flash attention (2-stage cp.async pipeline) ====================
#define STRK 144
#define STRV 272
#define F_KLO  (128 * STRK)            // 18432
#define F_VHI  (2 * 128 * STRK)        // 36864
#define F_VLO  (F_VHI + 64 * STRV)     // 54272
#define FSTAGE (F_VLO + 64 * STRV)     // 71680
#define SMEM_FLASH (2 * FSTAGE)        // 143360

__device__ __forceinline__ void flash_issue(uint32_t sbase, int stg, int tok0,
    const __nv_bfloat16* Kh, const __nv_bfloat16* Kl,
    const __nv_bfloat16* Vh, const __nv_bfloat16* Vl, int tid)
{
    const uint32_t s0 = sbase + stg * FSTAGE;
    #pragma unroll
    for (int i = 0; i < 4; i++) {
        int idx = tid + i * 256;
        int r = idx >> 3, c8 = idx & 7;
        uint32_t so = r * STRK + c8 * 16;
        CP_A16(s0 + so,          Kh + (long)(tok0 + r) * 1024 + c8 * 8);
        CP_A16(s0 + F_KLO + so,  Kl + (long)(tok0 + r) * 1024 + c8 * 8);
    }
    #pragma unroll
    for (int i = 0; i < 4; i++) {
        int idx = tid + i * 256;
        int r = idx >> 4, c = idx & 15;
        uint32_t so = r * STRV + c * 16;
        CP_A16(s0 + F_VHI + so,  Vh + (long)r * N_ + tok0 + c * 8);
        CP_A16(s0 + F_VLO + so,  Vl + (long)r * N_ + tok0 + c * 8);
    }
}

__global__ void __launch_bounds__(256, 1)
flash_attn(const __nv_bfloat16* __restrict__ qhi, const __nv_bfloat16* __restrict__ qlo,
           const __nv_bfloat16* __restrict__ khi, const __nv_bfloat16* __restrict__ klo,
           const __nv_bfloat16* __restrict__ vthi, const __nv_bfloat16* __restrict__ vtlo,
           __nv_bfloat16* __restrict__ chi, __nv_bfloat16* __restrict__ clo)
{
    extern __shared__ char smem[];
    const uint32_t sbase = smem_to_u32(smem);
    const int tid = threadIdx.x, warp = tid >> 5, lane = tid & 31;
    const int bh = blockIdx.y, b = bh >> 4, h = bh & 15;
    const int q0 = blockIdx.x * 128;

    const __nv_bfloat16* Qh = qhi + (long)(b * 1024 + q0) * 1024 + h * 64;
    const __nv_bfloat16* Ql = qlo + (long)(b * 1024 + q0) * 1024 + h * 64;
    const __nv_bfloat16* Kh = khi + (long)(b * 1024) * 1024 + h * 64;
    const __nv_bfloat16* Kl = klo + (long)(b * 1024) * 1024 + h * 64;
    const __nv_bfloat16* Vh = vthi + (long)bh * D_ * N_;
    const __nv_bfloat16* Vl = vtlo + (long)bh * D_ * N_;

    const int lrow = (lane & 7) | (((lane >> 3) & 1) << 3);
    const int lk8b = (lane >> 4) * 16;

    // ---- stage Q tile through stage-0 K area, lift fragments to registers ----
    #pragma unroll
    for (int i = 0; i < 4; i++) {
        int idx = tid + i * 256;
        int r = idx >> 3, c8 = idx & 7;
        *reinterpret_cast<uint4*>(smem + r * STRK + c8 * 16) =
            *reinterpret_cast<const uint4*>(Qh + (long)r * 1024 + c8 * 8);
        *reinterpret_cast<uint4*>(smem + F_KLO + r * STRK + c8 * 16) =
            *reinterpret_cast<const uint4*>(Ql + (long)r * 1024 + c8 * 8);
    }
    __syncthreads();
    uint32_t qh[4][4], ql[4][4];
    #pragma unroll
    for (int ks = 0; ks < 4; ks++) {
        uint32_t ao = sbase + (uint32_t)(warp * 16 + lrow) * STRK + ks * 32 + lk8b;
        LDSM_X4(qh[ks], ao);
        LDSM_X4(ql[ks], ao + F_KLO);
    }
    __syncthreads();   // frags read before chunk-0 copy overwrites stage 0

    float m0 = -INFINITY, m1 = -INFINITY;
    float l0 = 0.f, l1 = 0.f;
    float o[8][4];
    #pragma unroll
    for (int nf = 0; nf < 8; nf++)
        #pragma unroll
        for (int r = 0; r < 4; r++) o[nf][r] = 0.f;

    flash_issue(sbase, 0, 0, Kh, Kl, Vh, Vl, tid);
    CP_COMMIT();
    CP_WAIT0();
    __syncthreads();

    for (int t = 0; t < 8; t++) {
        const int st = t & 1;
        const uint32_t s0 = sbase + st * FSTAGE;
        if (t + 1 < 8) {
            flash_issue(sbase, (t + 1) & 1, (t + 1) * 128, Kh, Kl, Vh, Vl, tid);
            CP_COMMIT();
        }

        // ---- energy: S[16 rows][128 tok] per warp ----
        float s[16][4];
        #pragma unroll
        for (int nf = 0; nf < 16; nf++)
            #pragma unroll
            for (int r = 0; r < 4; r++) s[nf][r] = 0.f;

        #pragma unroll
        for (int ks = 0; ks < 4; ks++) {
            #pragma unroll
            for (int nf2 = 0; nf2 < 8; nf2++) {
                uint32_t bo = s0 + (uint32_t)(nf2 * 16 + lrow) * STRK + ks * 32 + lk8b;
                uint32_t bH[4], bL[4];
                LDSM_X4(bH, bo);
                LDSM_X4(bL, bo + F_KLO);
                MMA_BF16(s[2 * nf2],     qh[ks], bH[0], bH[2]);
                MMA_BF16(s[2 * nf2],     qh[ks], bL[0], bL[2]);
                MMA_BF16(s[2 * nf2],     ql[ks], bH[0], bH[2]);
                MMA_BF16(s[2 * nf2 + 1], qh[ks], bH[1], bH[3]);
                MMA_BF16(s[2 * nf2 + 1], qh[ks], bL[1], bL[3]);
                MMA_BF16(s[2 * nf2 + 1], ql[ks], bH[1], bH[3]);
            }
        }

        // ---- online softmax (rows lane>>2 and +8; stats intra-quad) ----
        float mx0 = -INFINITY, mx1 = -INFINITY;
        #pragma unroll
        for (int nf = 0; nf < 16; nf++) {
            mx0 = fmaxf(mx0, fmaxf(s[nf][0], s[nf][1]));
            mx1 = fmaxf(mx1, fmaxf(s[nf][2], s[nf][3]));
        }
        mx0 = fmaxf(mx0, __shfl_xor_sync(0xffffffffu, mx0, 1));
        mx0 = fmaxf(mx0, __shfl_xor_sync(0xffffffffu, mx0, 2));
        mx1 = fmaxf(mx1, __shfl_xor_sync(0xffffffffu, mx1, 1));
        mx1 = fmaxf(mx1, __shfl_xor_sync(0xffffffffu, mx1, 2));
        const float mn0 = fmaxf(m0, mx0), mn1 = fmaxf(m1, mx1);
        const float sc0 = __expf(m0 - mn0), sc1 = __expf(m1 - mn1);
        m0 = mn0; m1 = mn1;

        float sum0 = 0.f, sum1 = 0.f;
        #pragma unroll
        for (int nf = 0; nf < 16; nf++) {
            s[nf][0] = __expf(s[nf][0] - mn0);
            s[nf][1] = __expf(s[nf][1] - mn0);
            s[nf][2] = __expf(s[nf][2] - mn1);
            s[nf][3] = __expf(s[nf][3] - mn1);
            sum0 += s[nf][0] + s[nf][1];
            sum1 += s[nf][2] + s[nf][3];
        }
        sum0 += __shfl_xor_sync(0xffffffffu, sum0, 1);
        sum0 += __shfl_xor_sync(0xffffffffu, sum0, 2);
        sum1 += __shfl_xor_sync(0xffffffffu, sum1, 1);
        sum1 += __shfl_xor_sync(0xffffffffu, sum1, 2);
        l0 = l0 * sc0 + sum0;
        l1 = l1 * sc1 + sum1;
        #pragma unroll
        for (int nf = 0; nf < 8; nf++) {
            o[nf][0] *= sc0; o[nf][1] *= sc0;
            o[nf][2] *= sc1; o[nf][3] *= sc1;
        }

        // ---- AV: O[16 rows][64 d] += P @ V^T (P fragments straight from regs) ----
        #pragma unroll
        for (int kv = 0; kv < 8; kv++) {
            const float* f0 = s[2 * kv];
            const float* f1 = s[2 * kv + 1];
            uint32_t aH[4], aL[4];
            aH[0] = packbf(f0[0], f0[1]);
            aH[1] = packbf(f0[2], f0[3]);
            aH[2] = packbf(f1[0], f1[1]);
            aH[3] = packbf(f1[2], f1[3]);
            aL[0] = packbf(f0[0] - tobf(f0[0]), f0[1] - tobf(f0[1]));
            aL[1] = packbf(f0[2] - tobf(f0[2]), f0[3] - tobf(f0[3]));
            aL[2] = packbf(f1[0] - tobf(f1[0]), f1[1] - tobf(f1[1]));
            aL[3] = packbf(f1[2] - tobf(f1[2]), f1[3] - tobf(f1[3]));
            #pragma unroll
            for (int nd2 = 0; nd2 < 4; nd2++) {
                uint32_t vo = s0 + F_VHI + (uint32_t)(nd2 * 16 + lrow) * STRV + kv * 32 + lk8b;
                uint32_t vH[4], vL[4];
                LDSM_X4(vH, vo);
                LDSM_X4(vL, vo + (F_VLO - F_VHI));
                MMA_BF16(o[2 * nd2],     aH, vH[0], vH[2]);
                MMA_BF16(o[2 * nd2],     aL, vH[0], vH[2]);
                MMA_BF16(o[2 * nd2],     aH, vL[0], vL[2]);
                MMA_BF16(o[2 * nd2 + 1], aH, vH[1], vH[3]);
                MMA_BF16(o[2 * nd2 + 1], aL, vH[1], vH[3]);
                MMA_BF16(o[2 * nd2 + 1], aH, vL[1], vL[3]);
            }
        }

        if (t + 1 < 8) { CP_WAIT0(); __syncthreads(); }
    }

    // ---- epilogue: normalize by 1/(l * sqrt(E)), store ctx hi/lo ----
    const float inv0 = 1.0f / (l0 * 32.0f);
    const float inv1 = 1.0f / (l1 * 32.0f);
    const int gr = b * 1024 + q0 + warp * 16 + (lane >> 2);
    const int colb = h * 64 + (lane & 3) * 2;
    #pragma unroll
    for (int nf = 0; nf < 8; nf++) {
        int col = colb + nf * 8;
        float v0 = o[nf][0] * inv0, v1 = o[nf][1] * inv0;
        float v2 = o[nf][2] * inv1, v3 = o[nf][3] * inv1;
        long o0 = (long)gr * 1024 + col;
        long o8 = (long)(gr + 8) * 1024 + col;
        *reinterpret_cast<uint32_t*>(chi + o0) = packbf(v0, v1);
        *reinterpret_cast<uint32_t*>(clo + o0) = packbf(v0 - tobf(v0), v1 - tobf(v1));
        *reinterpret_cast<uint32_t*>(chi + o8) = packbf(v2, v3);
        *reinterpret_cast<uint32_t*>(clo + o8) = packbf(v2 - tobf(v2), v3 - tobf(v3));
    }
}

// ==================== launch ====================
extern "C" void kernel_launch(void* const* d_in, const int* in_sizes, int n_in,
                              void* d_out, int out_size)
{
    const float* x  = (const float*)d_in[0];
    const float* Wq = (const float*)d_in[1];
    const float* bq = (const float*)d_in[2];
    const float* Wk = (const float*)d_in[3];
    const float* bk = (const float*)d_in[4];
    const float* Wv = (const float*)d_in[5];
    const float* bv = (const float*)d_in[6];
    const float* Wo = (const float*)d_in[7];
    const float* bo = (const float*)d_in[8];
    float* out = (float*)d_out;

    __nv_bfloat16 *xhi, *xlo, *wqh, *wql, *wkh, *wkl, *wvh, *wvl, *woh, *wol;
    __nv_bfloat16 *qhi, *qlo, *khi, *klo, *vthi, *vtlo, *chi, *clo;
    cudaGetSymbolAddress((void**)&xhi, g_xhi);   cudaGetSymbolAddress((void**)&xlo, g_xlo);
    cudaGetSymbolAddress((void**)&wqh, g_wqh);   cudaGetSymbolAddress((void**)&wql, g_wql);
    cudaGetSymbolAddress((void**)&wkh, g_wkh);   cudaGetSymbolAddress((void**)&wkl, g_wkl);
    cudaGetSymbolAddress((void**)&wvh, g_wvh);   cudaGetSymbolAddress((void**)&wvl, g_wvl);
    cudaGetSymbolAddress((void**)&woh, g_woh);   cudaGetSymbolAddress((void**)&wol, g_wol);
    cudaGetSymbolAddress((void**)&qhi, g_qhi);   cudaGetSymbolAddress((void**)&qlo, g_qlo);
    cudaGetSymbolAddress((void**)&khi, g_khi);   cudaGetSymbolAddress((void**)&klo, g_klo);
    cudaGetSymbolAddress((void**)&vthi, g_vthi); cudaGetSymbolAddress((void**)&vtlo, g_vtlo);
    cudaGetSymbolAddress((void**)&chi, g_chi);   cudaGetSymbolAddress((void**)&clo, g_clo);

    cudaFuncSetAttribute(gemm_qkv,  cudaFuncAttributeMaxDynamicSharedMemorySize, GSMEM);
    cudaFuncSetAttribute(gemm_out,  cudaFuncAttributeMaxDynamicSharedMemorySize, GSMEM);
    cudaFuncSetAttribute(flash_attn, cudaFuncAttributeMaxDynamicSharedMemorySize, SMEM_FLASH);

    // ---- split inputs/weights to bf16 hi/lo ----
    split_bf16<<<(MTOT * E_) / 1024, 256>>>(x, xhi, xlo, MTOT * E_);
    split_bf16<<<(E_ * E_) / 1024, 256>>>(Wq, wqh, wql, E_ * E_);
    split_bf16<<<(E_ * E_) / 1024, 256>>>(Wk, wkh, wkl, E_ * E_);
    split_bf16<<<(E_ * E_) / 1024, 256>>>(Wv, wvh, wvl, E_ * E_);
    split_bf16<<<(E_ * E_) / 1024, 256>>>(Wo, woh, wol, E_ * E_);

    // ---- merged QKV projections (one launch, weight picked per CTA) ----
    {
        dim3 g(24, MTOT / 128);    // x: 3 weights x 8 col tiles
        gemm_qkv<<<g, 256, GSMEM>>>(xhi, xlo, wqh, wql, wkh, wkl, wvh, wvl,
                                    bq, bk, bv, qhi, qlo, khi, klo, vthi, vtlo);
    }

    // ---- fused attention ----
    {
        dim3 g(N_ / 128, BHN);
        flash_attn<<<g, 256, SMEM_FLASH>>>(qhi, qlo, khi, klo, vthi, vtlo, chi, clo);
    }

    // ---- output projection ----
    {
        dim3 g(E_ / 128, MTOT / 128);
        gemm_out<<<g, 256, GSMEM>>>(chi, clo, woh, wol, bo, out);
    }
}